// round 6
// baseline (speedup 1.0000x reference)
#include <cuda_runtime.h>
#include <math.h>
#include <stdint.h>

// Problem constants
#define BB 64
#define CC 16
#define FF 2048
#define JT 25            // stored joints per feature row
#define SPB 8            // series per block (8 of the 24 used joints)
#define NT 256           // 8 warps, one per series
#define RS 2052          // padded row stride (words): conflict-free ph1+ph2
#define HIST_OFF (SPB * RS)
#define SMEM_WORDS (SPB * RS + SPB * 256)
#define SMEM_BYTES (SMEM_WORDS * 4)

__device__ float g_stat2[BB * CC * 16 * 12];   // (b, c, s, j)
__device__ float g_weff[5 * 16 * 16 * 12];     // (cls, c, s, j)

// ---------------------------------------------------------------------------
// 256-bin histogram rank search (warp-uniform r). Returns bin; updates r to
// rank-within-bin; outputs the bin's count.
// ---------------------------------------------------------------------------
__device__ __forceinline__ int warp_find_bin256(const unsigned* hist, int lane,
                                                int& r, int& bincount) {
    const unsigned full = 0xffffffffu;
    unsigned c[8]; unsigned run = 0;
#pragma unroll
    for (int t = 0; t < 8; t++) { c[t] = hist[lane * 8 + t]; run += c[t]; }
    unsigned inc = run;
#pragma unroll
    for (int d = 1; d < 32; d <<= 1) {
        unsigned v = __shfl_up_sync(full, inc, d);
        if (lane >= d) inc += v;
    }
    unsigned acc = inc - run;
    int bin = -1, newr = 0; unsigned bc = 0;
#pragma unroll
    for (int t = 0; t < 8; t++) {
        if (bin < 0 && (int)acc <= r && r < (int)(acc + c[t])) {
            bin = lane * 8 + t;
            newr = r - (int)acc;
            bc = c[t];
        }
        acc += c[t];
    }
    unsigned m = __ballot_sync(full, bin >= 0);
    int srcl = __ffs(m) - 1;
    bin      = __shfl_sync(full, bin, srcl);
    newr     = __shfl_sync(full, newr, srcl);
    bc       = __shfl_sync(full, bc, srcl);
    r = newr;
    bincount = (int)bc;
    return bin;
}

__device__ __forceinline__ unsigned f2key(float x) {
    unsigned b = __float_as_uint(x);
    return b ^ ((unsigned)(((int)b) >> 31) | 0x80000000u);
}

// ---------------------------------------------------------------------------
// Kernel A: one block per (b,c,part); 8 warps, one series each.
// No level-1 histogram: pivot counting in registers (ALU), value-bracket
// gather into smem, byte-radix refinement on the small candidate set,
// final <=32 bitonic sort in registers.
// ---------------------------------------------------------------------------
__global__ __launch_bounds__(NT, 2)
void stats_kernel(const float* __restrict__ features) {
    extern __shared__ unsigned sm[];
    const unsigned full = 0xffffffffu;

    const int blk  = blockIdx.x;
    const int bc   = blk / 3;
    const int part = blk - bc * 3;       // 0..2 -> joints part*8 .. +7
    const int tid  = threadIdx.x;

    const float* src = features + (size_t)bc * (FF * JT) + part * 8;
    float* smf = reinterpret_cast<float*>(sm);

    // ---- phase 1: load the 8 needed joints, transpose to rows ----
    {
        int jj = tid & 7;
        int f  = tid >> 3;               // 0..31
#pragma unroll 8
        for (int k = 0; k < 64; k++, f += 32)
            smf[jj * RS + f] = __ldg(src + f * JT + jj);
    }
    __syncthreads();

    const int w    = tid >> 5;
    const int lane = tid & 31;

    // ---- phase 2: series -> registers; moments; monotone sortable keys ----
    unsigned key[64];
    float s1 = 0.f, s2 = 0.f, s3 = 0.f, s4 = 0.f;
    float mn = INFINITY, mx = -INFINITY;
    const unsigned* row = sm + w * RS;
#pragma unroll
    for (int i = 0; i < 64; i++) {
        unsigned raw = row[i * 32 + lane];
        float x = __uint_as_float(raw);
        s1 += x;
        float x2 = x * x;
        s2 += x2; s3 += x2 * x; s4 += x2 * x2;
        mn = fminf(mn, x); mx = fmaxf(mx, x);
        key[i] = raw ^ ((unsigned)(((int)raw) >> 31) | 0x80000000u);
    }
#pragma unroll
    for (int d = 16; d; d >>= 1) {
        s1 += __shfl_xor_sync(full, s1, d);
        s2 += __shfl_xor_sync(full, s2, d);
        s3 += __shfl_xor_sync(full, s3, d);
        s4 += __shfl_xor_sync(full, s4, d);
        mn = fminf(mn, __shfl_xor_sync(full, mn, d));
        mx = fmaxf(mx, __shfl_xor_sync(full, mx, d));
    }
    // (no block barrier needed: each warp only reuses ITS OWN row below)

    // ---- moments (all lanes, redundantly; needed for pivots) ----
    const float n = 2048.f;
    float mean = s1 / n;
    float m2 = s2 / n, m3 = s3 / n, m4 = s4 / n;
    float varp = m2 - mean * mean;
    float var1 = varp * (n / (n - 1.f));
    float sd = sqrtf(var1);

    // ---- phase 3: 6 pivot counts from registers (pure ALU) ----
    const float Z[6] = {-0.775f, -0.575f, -0.115f, 0.115f, 0.575f, 0.775f};
    unsigned pk[6];
#pragma unroll
    for (int k = 0; k < 6; k++) pk[k] = f2key(fmaf(sd, Z[k], mean));
    int c[6] = {0, 0, 0, 0, 0, 0};
#pragma unroll
    for (int i = 0; i < 64; i++) {
        unsigned k = key[i];
#pragma unroll
        for (int t = 0; t < 6; t++) c[t] += (k < pk[t]);
    }
#pragma unroll
    for (int d = 16; d; d >>= 1) {
#pragma unroll
        for (int t = 0; t < 6; t++) c[t] += __shfl_xor_sync(full, c[t], d);
    }

    // ---- phase 4: per-rank bracket gather + byte-radix select ----
    unsigned* buf = sm + w * RS;            // data row is dead -> reuse
    unsigned* h2  = sm + HIST_OFF + w * 256;
    const int ranks[5] = {511, 512, 1023, 1535, 1536};
    float qv[5];
    unsigned havemask = 0;

#pragma unroll 1
    for (int q = 0; q < 5; q++) {
        if (havemask & (1u << q)) continue;
        int r = ranks[q];

        // bracket: [Klo, Khi) with global ranks [lo, hi). Exact by
        // construction: same key-compare used for counts and gather.
        int lo = 0, hi = 2048;
        unsigned Klo = 0u, Khi = 0xFFFFFFFFu;
#pragma unroll
        for (int m = 0; m < 6; m++)
            if (r >= c[m]) { lo = c[m]; Klo = pk[m]; }
#pragma unroll
        for (int m = 5; m >= 0; m--)
            if (r < c[m]) { hi = c[m]; Khi = pk[m]; }
        int lr  = r - lo;
        int cnt = hi - lo;

        // gather candidates into buf
        {
            int pos = 0;
#pragma unroll
            for (int i = 0; i < 64; i++) {
                unsigned k = key[i];
                bool p = (k >= Klo) && (k < Khi);
                unsigned m = __ballot_sync(full, p);
                if (p) buf[pos + __popc(m & ((1u << lane) - 1u))] = k;
                pos += __popc(m);
            }
            __syncwarp();
        }

        // byte-radix refinement (atomics only over ~cnt candidates)
        unsigned assembled = 0;
        int sh = 24;
#pragma unroll 1
        while (cnt > 32 && sh >= 0) {
            for (int t = 0; t < 8; t++) h2[lane + t * 32] = 0u;
            __syncwarp();
            for (int idx = lane; idx < cnt; idx += 32)
                atomicAdd(&h2[(buf[idx] >> sh) & 0xFFu], 1u);
            __syncwarp();
            int bcnt;
            int b = warp_find_bin256(h2, lane, lr, bcnt);
            __syncwarp();
            // compact in place
            int nc = 0;
            for (int base = 0; base < cnt; base += 32) {
                int idx = base + lane;
                unsigned kk = (idx < cnt) ? buf[idx] : 0u;
                bool p = (idx < cnt) && (((kk >> sh) & 0xFFu) == (unsigned)b);
                unsigned m = __ballot_sync(full, p);
                __syncwarp();
                if (p) buf[nc + __popc(m & ((1u << lane) - 1u))] = kk;
                nc += __popc(m);
            }
            assembled |= (unsigned)b << sh;
            cnt = bcnt;
            sh -= 8;
            __syncwarp();
        }

        unsigned k0, k1;
        bool has1 = (lr + 1 < cnt);
        if (cnt <= 32) {
            unsigned v = (lane < cnt) ? buf[lane] : 0xFFFFFFFFu;
#pragma unroll
            for (int k2 = 2; k2 <= 32; k2 <<= 1) {
#pragma unroll
                for (int j = k2 >> 1; j > 0; j >>= 1) {
                    unsigned o = __shfl_xor_sync(full, v, j);
                    bool keepMin = ((lane & j) == 0) == ((lane & k2) == 0);
                    unsigned l2 = min(v, o), h3 = max(v, o);
                    v = keepMin ? l2 : h3;
                }
            }
            k0 = __shfl_sync(full, v, lr);
            k1 = __shfl_sync(full, v, (lr + 1) & 31);
        } else {
            // all 4 byte stages ran and one bin held everything:
            // every surviving key is bit-identical == assembled
            k0 = assembled;
            k1 = assembled;
        }

        unsigned u0 = (k0 & 0x80000000u) ? (k0 & 0x7fffffffu) : ~k0;
        qv[q] = __uint_as_float(u0);
        if ((q == 0 || q == 3) && has1) {
            unsigned u1 = (k1 & 0x80000000u) ? (k1 & 0x7fffffffu) : ~k1;
            qv[q + 1] = __uint_as_float(u1);
            havemask |= 1u << (q + 1);
        }
    }

    // ---- phase 5: finalize + write stat2 ----
    if (lane == 0) {
        float mu2 = mean * mean;
        float m4c = m4 - 4.f * mean * m3 + 6.f * mu2 * m2 - 3.f * mu2 * mu2;
        float kurt = m4c / (var1 * var1) - 3.f;
        float q25 = 0.25f * qv[0] + 0.75f * qv[1];   // pos 511.75
        float med = qv[2];                            // pos 1023
        float q75 = 0.75f * qv[3] + 0.25f * qv[4];   // pos 1535.25

        int jg = part * 8 + w;                        // 0..23
        int base = (jg < 12) ? 0 : 8;
        int col  = (jg < 12) ? jg : (jg - 12);
        float* o = g_stat2 + ((size_t)bc * 16 + base) * 12 + col;
        o[0 * 12] = mx;
        o[1 * 12] = q25;
        o[2 * 12] = med;
        o[3 * 12] = q75;
        o[4 * 12] = mean;
        o[5 * 12] = sd;
        o[6 * 12] = mx - mn;
        o[7 * 12] = kurt;
    }
}

// ---------------------------------------------------------------------------
// Kernel B: Weff[cls,c,s,j] = sum_e Wl[cls,e*16+s] * W2[e,c,j]
// ---------------------------------------------------------------------------
__global__ __launch_bounds__(128)
void weff_kernel(const float* __restrict__ W2, const float* __restrict__ Wl) {
    int idx = blockIdx.x * 128 + threadIdx.x;
    if (idx >= 5 * 3072) return;
    int j   = idx % 12;
    int s   = (idx / 12) & 15;
    int cx  = (idx / 192) & 15;
    int cls = idx / 3072;
    float a = 0.f;
#pragma unroll 8
    for (int e = 0; e < 64; e++)
        a += __ldg(&Wl[cls * 1024 + e * 16 + s]) * __ldg(&W2[(e * 16 + cx) * 12 + j]);
    g_weff[idx] = a;
}

// ---------------------------------------------------------------------------
// Kernel C: logits[b,cls] = dot(stat2[b], weff[cls]) + sum b2*Wl + bl
// one block per output (320 blocks x 128 threads).
// ---------------------------------------------------------------------------
__global__ __launch_bounds__(128)
void logits_kernel(const float* __restrict__ Wl, const float* __restrict__ b2,
                   const float* __restrict__ bl, float* __restrict__ out) {
    __shared__ float part[4];
    const unsigned full = 0xffffffffu;
    int blk = blockIdx.x;
    int b = blk / 5, cls = blk - b * 5;
    int tid = threadIdx.x;
    const float* st = g_stat2 + (size_t)b * 3072;
    const float* wf = g_weff + (size_t)cls * 3072;
    float a = 0.f;
    for (int i = tid; i < 3072; i += 128) a += st[i] * wf[i];
    for (int k = tid; k < 1024; k += 128)
        a += __ldg(&b2[k >> 4]) * __ldg(&Wl[cls * 1024 + k]);
#pragma unroll
    for (int d = 16; d; d >>= 1) a += __shfl_xor_sync(full, a, d);
    if ((tid & 31) == 0) part[tid >> 5] = a;
    __syncthreads();
    if (tid == 0)
        out[b * 5 + cls] = part[0] + part[1] + part[2] + part[3] + bl[cls];
}

// ---------------------------------------------------------------------------
extern "C" void kernel_launch(void* const* d_in, const int* in_sizes, int n_in,
                              void* d_out, int out_size) {
    const float* features = (const float*)d_in[0];
    // d_in[1]=W1, d_in[2]=b1 : dead in the reference (result discarded)
    const float* W2 = (const float*)d_in[3];
    const float* b2 = (const float*)d_in[4];
    const float* Wl = (const float*)d_in[5];
    const float* bl = (const float*)d_in[6];
    float* out = (float*)d_out;

    cudaFuncSetAttribute(stats_kernel,
                         cudaFuncAttributeMaxDynamicSharedMemorySize,
                         SMEM_BYTES);

    stats_kernel<<<BB * CC * 3, NT, SMEM_BYTES>>>(features);
    weff_kernel<<<(5 * 3072 + 127) / 128, 128>>>(W2, Wl);
    logits_kernel<<<BB * 5, 128>>>(Wl, b2, bl, out);
}

// round 7
// speedup vs baseline: 1.6682x; 1.6682x over previous
#include <cuda_runtime.h>
#include <math.h>
#include <stdint.h>

// Problem constants
#define BB 64
#define CC 16
#define FF 2048
#define JT 25            // stored joints per feature row
#define SPB 8            // series per block
#define NT 256           // 8 warps, one per series
#define RS 2052          // padded row stride (words): conflict-free
#define WCAP 256         // per-window candidate capacity (words)
#define CAND_OFF (SPB * RS)                     // 16416
#define HIST_OFF (CAND_OFF + SPB * 3 * WCAP)    // 22560
#define SMEM_WORDS (HIST_OFF + SPB * 256)       // 24608
#define SMEM_BYTES (SMEM_WORDS * 4)             // 98432

__device__ float g_stat2[BB * CC * 16 * 12];   // (b, c, s, j)
__device__ float g_weff[5 * 16 * 16 * 12];     // (cls, c, s, j)

__device__ __forceinline__ unsigned f2key(float x) {
    unsigned b = __float_as_uint(x);
    return b ^ ((unsigned)(((int)b) >> 31) | 0x80000000u);
}
__device__ __forceinline__ float key2f(unsigned k) {
    unsigned u = (k & 0x80000000u) ? (k & 0x7fffffffu) : ~k;
    return __uint_as_float(u);
}

// ---------------------------------------------------------------------------
// 256-bin histogram rank search (warp-uniform r). Returns bin; updates r to
// rank-within-bin; outputs bin count.
// ---------------------------------------------------------------------------
__device__ __forceinline__ int warp_find_bin256(const unsigned* hist, int lane,
                                                int& r, int& bincount) {
    const unsigned full = 0xffffffffu;
    unsigned c[8]; unsigned run = 0;
#pragma unroll
    for (int t = 0; t < 8; t++) { c[t] = hist[lane * 8 + t]; run += c[t]; }
    unsigned inc = run;
#pragma unroll
    for (int d = 1; d < 32; d <<= 1) {
        unsigned v = __shfl_up_sync(full, inc, d);
        if (lane >= d) inc += v;
    }
    unsigned acc = inc - run;
    int bin = -1, newr = 0; unsigned bc = 0;
#pragma unroll
    for (int t = 0; t < 8; t++) {
        if (bin < 0 && (int)acc <= r && r < (int)(acc + c[t])) {
            bin = lane * 8 + t; newr = r - (int)acc; bc = c[t];
        }
        acc += c[t];
    }
    unsigned m = __ballot_sync(full, bin >= 0);
    int srcl = __ffs(m) - 1;
    bin  = __shfl_sync(full, bin, srcl);
    newr = __shfl_sync(full, newr, srcl);
    bc   = __shfl_sync(full, bc, srcl);
    r = newr; bincount = (int)bc;
    return bin;
}

// ---------------------------------------------------------------------------
// Select ranks lr and lr+1 from cnt FLOAT candidates in buf (destroyed).
// k1 (.y) is valid whenever rank lr+1 existed in the original candidate set
// (caller guarantees lr+1 < cnt on entry when it needs .y). Uses adaptive-
// shift byte radix + minAbove tracking so the pair never needs a re-gather.
// ---------------------------------------------------------------------------
__device__ uint2 select_pair(unsigned* buf, unsigned* hist, int cnt, int lr, int lane) {
    const unsigned full = 0xffffffffu;
    unsigned kmn = 0xffffffffu, kmx = 0u;
    for (int idx = lane; idx < cnt; idx += 32) {
        unsigned k = f2key(__uint_as_float(buf[idx]));
        buf[idx] = k;
        kmn = min(kmn, k); kmx = max(kmx, k);
    }
#pragma unroll
    for (int d = 16; d; d >>= 1) {
        kmn = min(kmn, __shfl_xor_sync(full, kmn, d));
        kmx = max(kmx, __shfl_xor_sync(full, kmx, d));
    }
    __syncwarp();
    unsigned minAbove = 0xffffffffu;
#pragma unroll 1
    while (cnt > 32) {
        unsigned diff = kmn ^ kmx;
        if (diff == 0u) {   // all survivors identical
            unsigned k1 = (lr + 1 < cnt) ? kmn : minAbove;
            return make_uint2(kmn, k1);
        }
        int hib = 31 - __clz(diff);
        int sh = hib > 7 ? hib - 7 : 0;
#pragma unroll
        for (int t = 0; t < 8; t++) hist[lane + t * 32] = 0u;
        __syncwarp();
        for (int idx = lane; idx < cnt; idx += 32)
            atomicAdd(&hist[(buf[idx] >> sh) & 0xFFu], 1u);
        __syncwarp();
        int bcnt;
        int b = warp_find_bin256(hist, lane, lr, bcnt);
        __syncwarp();
        unsigned nmn = 0xffffffffu, nmx = 0u, mna = 0xffffffffu;
        int nc = 0;
        for (int base = 0; base < cnt; base += 32) {
            int idx = base + lane;
            unsigned kk = (idx < cnt) ? buf[idx] : 0u;
            unsigned bb = (kk >> sh) & 0xFFu;
            bool valid = idx < cnt;
            bool p = valid && (bb == (unsigned)b);
            if (valid && (int)bb > b) mna = min(mna, kk);
            unsigned m = __ballot_sync(full, p);
            __syncwarp();
            if (p) {
                buf[nc + __popc(m & ((1u << lane) - 1u))] = kk;
                nmn = min(nmn, kk); nmx = max(nmx, kk);
            }
            nc += __popc(m);
        }
#pragma unroll
        for (int d = 16; d; d >>= 1) {
            nmn = min(nmn, __shfl_xor_sync(full, nmn, d));
            nmx = max(nmx, __shfl_xor_sync(full, nmx, d));
            mna = min(mna, __shfl_xor_sync(full, mna, d));
        }
        minAbove = min(minAbove, mna);
        kmn = nmn; kmx = nmx; cnt = bcnt;
        __syncwarp();
    }
    unsigned v = (lane < cnt) ? buf[lane] : 0xffffffffu;
#pragma unroll
    for (int k2 = 2; k2 <= 32; k2 <<= 1)
#pragma unroll
        for (int j = k2 >> 1; j; j >>= 1) {
            unsigned o = __shfl_xor_sync(full, v, j);
            bool keepMin = ((lane & j) == 0) == ((lane & k2) == 0);
            v = keepMin ? min(v, o) : max(v, o);
        }
    unsigned k0  = __shfl_sync(full, v, lr);
    unsigned k1n = __shfl_sync(full, v, (lr + 1) & 31);
    unsigned k1  = (lr + 1 < cnt) ? k1n : minAbove;
    return make_uint2(k0, k1);
}

// ---------------------------------------------------------------------------
// Correctness fallback: exact rank-r key via value bisection over the intact
// smem row. Never triggers for normal data; bounded 32 passes.
// ---------------------------------------------------------------------------
__device__ unsigned generic_select_row(const unsigned* row, int lane, int r) {
    const unsigned full = 0xffffffffu;
    unsigned Klo = 0u, Khi = 0xffffffffu;
#pragma unroll 1
    while (Klo < Khi) {
        unsigned mid = Klo + ((Khi - Klo) >> 1);
        int cle = 0;
        for (int i = 0; i < 64; i++) {
            unsigned k = f2key(__uint_as_float(row[i * 32 + lane]));
            cle += (k <= mid);
        }
#pragma unroll
        for (int d = 16; d; d >>= 1) cle += __shfl_xor_sync(full, cle, d);
        if (r < cle) Khi = mid; else Klo = mid + 1u;
    }
    return Klo;
}

// ---------------------------------------------------------------------------
// Kernel A: one block per (b,c,part); 8 warps, one series each.
// Single fused smem pass: moments + min/max + pivot counts + window gather.
// No register-resident key array -> no spills, 2 blocks/SM.
// ---------------------------------------------------------------------------
__global__ __launch_bounds__(NT, 2)
void stats_kernel(const float* __restrict__ features,
                  const float* __restrict__ W2, const float* __restrict__ Wl) {
    extern __shared__ unsigned sm[];
    const unsigned full = 0xffffffffu;

    const int blk  = blockIdx.x;
    const int bc   = blk / 3;
    const int part = blk - bc * 3;
    const int tid  = threadIdx.x;

    const float* src = features + (size_t)bc * (FF * JT) + part * 8;
    float* smf = reinterpret_cast<float*>(sm);

    // ---- phase 1: load the 8 needed joints, transpose to rows ----
    {
        int jj = tid & 7;
        int f  = tid >> 3;
#pragma unroll 8
        for (int k = 0; k < 64; k++, f += 32)
            smf[jj * RS + f] = __ldg(src + f * JT + jj);
    }
    __syncthreads();

    const int w    = tid >> 5;
    const int lane = tid & 31;
    const unsigned* row = sm + w * RS;
    unsigned* cand = sm + CAND_OFF + w * (3 * WCAP);
    unsigned* hist = sm + HIST_OFF + w * 256;

    // fixed pivots (data ~N(0,1); fallback keeps this correct regardless)
    const float P0 = -0.80f, P1 = -0.55f, P2 = -0.125f,
                P3 =  0.125f, P4 =  0.55f, P5 =  0.80f;

    // ---- fused pass: moments + counts + 3-window gather ----
    float s1 = 0.f, s2 = 0.f, s3 = 0.f, s4 = 0.f;
    float mn = INFINITY, mx = -INFINITY;
    int cA = 0, cC = 0, cE = 0;
    int p0 = 0, p1 = 0, p2 = 0;           // warp-uniform window fills
#pragma unroll 4
    for (int i = 0; i < 64; i++) {
        float x = __uint_as_float(row[i * 32 + lane]);
        s1 += x;
        float x2 = x * x;
        s2 += x2; s3 += x2 * x; s4 += x2 * x2;
        mn = fminf(mn, x); mx = fmaxf(mx, x);
        bool b0 = x < P0, b1 = x < P1, b2 = x < P2,
             b3 = x < P3, b4 = x < P4, b5 = x < P5;
        cA += b0; cC += b2; cE += b4;
        bool w0 = b1 && !b0, w1 = b3 && !b2, w2 = b5 && !b4;
        unsigned m0 = __ballot_sync(full, w0);
        if (w0) { int pos = p0 + __popc(m0 & ((1u << lane) - 1u));
                  if (pos < WCAP) cand[pos] = __float_as_uint(x); }
        p0 += __popc(m0);
        unsigned m1 = __ballot_sync(full, w1);
        if (w1) { int pos = p1 + __popc(m1 & ((1u << lane) - 1u));
                  if (pos < WCAP) cand[WCAP + pos] = __float_as_uint(x); }
        p1 += __popc(m1);
        unsigned m2 = __ballot_sync(full, w2);
        if (w2) { int pos = p2 + __popc(m2 & ((1u << lane) - 1u));
                  if (pos < WCAP) cand[2 * WCAP + pos] = __float_as_uint(x); }
        p2 += __popc(m2);
    }
#pragma unroll
    for (int d = 16; d; d >>= 1) {
        s1 += __shfl_xor_sync(full, s1, d);
        s2 += __shfl_xor_sync(full, s2, d);
        s3 += __shfl_xor_sync(full, s3, d);
        s4 += __shfl_xor_sync(full, s4, d);
        mn = fminf(mn, __shfl_xor_sync(full, mn, d));
        mx = fmaxf(mx, __shfl_xor_sync(full, mx, d));
        cA += __shfl_xor_sync(full, cA, d);
        cC += __shfl_xor_sync(full, cC, d);
        cE += __shfl_xor_sync(full, cE, d);
    }
    __syncwarp();

    // ---- selections ----
    float qv[5];
    {   // ranks 511, 512
        int lr = 511 - cA;
        if (lr >= 0 && 512 < cA + p0 && p0 <= WCAP) {
            uint2 kk = select_pair(cand, hist, p0, lr, lane);
            qv[0] = key2f(kk.x); qv[1] = key2f(kk.y);
        } else {
            qv[0] = key2f(generic_select_row(row, lane, 511));
            qv[1] = key2f(generic_select_row(row, lane, 512));
        }
    }
    {   // rank 1023
        int lr = 1023 - cC;
        if (lr >= 0 && 1023 < cC + p1 && p1 <= WCAP) {
            uint2 kk = select_pair(cand + WCAP, hist, p1, lr, lane);
            qv[2] = key2f(kk.x);
        } else {
            qv[2] = key2f(generic_select_row(row, lane, 1023));
        }
    }
    {   // ranks 1535, 1536
        int lr = 1535 - cE;
        if (lr >= 0 && 1536 < cE + p2 && p2 <= WCAP) {
            uint2 kk = select_pair(cand + 2 * WCAP, hist, p2, lr, lane);
            qv[3] = key2f(kk.x); qv[4] = key2f(kk.y);
        } else {
            qv[3] = key2f(generic_select_row(row, lane, 1535));
            qv[4] = key2f(generic_select_row(row, lane, 1536));
        }
    }

    // ---- finalize + write stat2 ----
    if (lane == 0) {
        const float n = 2048.f;
        float mean = s1 / n;
        float m2 = s2 / n, m3 = s3 / n, m4 = s4 / n;
        float varp = m2 - mean * mean;
        float var1 = varp * (n / (n - 1.f));
        float sd = sqrtf(var1);
        float mu2 = mean * mean;
        float m4c = m4 - 4.f * mean * m3 + 6.f * mu2 * m2 - 3.f * mu2 * mu2;
        float kurt = m4c / (var1 * var1) - 3.f;
        float q25 = 0.25f * qv[0] + 0.75f * qv[1];   // pos 511.75
        float med = qv[2];                            // pos 1023
        float q75 = 0.75f * qv[3] + 0.25f * qv[4];   // pos 1535.25

        int jg = part * 8 + w;
        int base = (jg < 12) ? 0 : 8;
        int col  = (jg < 12) ? jg : (jg - 12);
        float* o = g_stat2 + ((size_t)bc * 16 + base) * 12 + col;
        o[0 * 12] = mx;
        o[1 * 12] = q25;
        o[2 * 12] = med;
        o[3 * 12] = q75;
        o[4 * 12] = mean;
        o[5 * 12] = sd;
        o[6 * 12] = mx - mn;
        o[7 * 12] = kurt;
    }

    // ---- weff tail folded in: blocks 0..119, threads 0..127 ----
    if (blk < 120 && tid < 128) {
        int idx = blk * 128 + tid;                 // 0 .. 15359
        int j   = idx % 12;
        int s   = (idx / 12) & 15;
        int cx  = (idx / 192) & 15;
        int cls = idx / 3072;
        float a = 0.f;
#pragma unroll 8
        for (int e = 0; e < 64; e++)
            a += __ldg(&Wl[cls * 1024 + e * 16 + s]) *
                 __ldg(&W2[(e * 16 + cx) * 12 + j]);
        g_weff[idx] = a;
    }
}

// ---------------------------------------------------------------------------
// Kernel B: logits[b,cls] = dot(stat2[b], weff[cls]) + sum b2*Wl + bl
// ---------------------------------------------------------------------------
__global__ __launch_bounds__(128)
void logits_kernel(const float* __restrict__ Wl, const float* __restrict__ b2,
                   const float* __restrict__ bl, float* __restrict__ out) {
    __shared__ float part[4];
    const unsigned full = 0xffffffffu;
    int blk = blockIdx.x;
    int b = blk / 5, cls = blk - b * 5;
    int tid = threadIdx.x;
    const float* st = g_stat2 + (size_t)b * 3072;
    const float* wf = g_weff + (size_t)cls * 3072;
    float a = 0.f;
    for (int i = tid; i < 3072; i += 128) a += st[i] * wf[i];
    for (int k = tid; k < 1024; k += 128)
        a += __ldg(&b2[k >> 4]) * __ldg(&Wl[cls * 1024 + k]);
#pragma unroll
    for (int d = 16; d; d >>= 1) a += __shfl_xor_sync(full, a, d);
    if ((tid & 31) == 0) part[tid >> 5] = a;
    __syncthreads();
    if (tid == 0)
        out[b * 5 + cls] = part[0] + part[1] + part[2] + part[3] + bl[cls];
}

// ---------------------------------------------------------------------------
extern "C" void kernel_launch(void* const* d_in, const int* in_sizes, int n_in,
                              void* d_out, int out_size) {
    const float* features = (const float*)d_in[0];
    // d_in[1]=W1, d_in[2]=b1 : dead in the reference (result discarded)
    const float* W2 = (const float*)d_in[3];
    const float* b2 = (const float*)d_in[4];
    const float* Wl = (const float*)d_in[5];
    const float* bl = (const float*)d_in[6];
    float* out = (float*)d_out;

    cudaFuncSetAttribute(stats_kernel,
                         cudaFuncAttributeMaxDynamicSharedMemorySize,
                         SMEM_BYTES);

    stats_kernel<<<BB * CC * 3, NT, SMEM_BYTES>>>(features, W2, Wl);
    logits_kernel<<<BB * 5, 128>>>(Wl, b2, bl, out);
}

// round 8
// speedup vs baseline: 1.8916x; 1.1339x over previous
#include <cuda_runtime.h>
#include <math.h>
#include <stdint.h>

// Problem constants
#define BB 64
#define CC 16
#define FF 2048
#define JT 25            // stored joints per feature row
#define SPB 4            // series per block
#define NPARTS 6         // 24 joints / 4
#define NT 256           // 8 warps: 2 per series
#define RS 2056          // padded row stride (words): mod 32 == 8
#define CAPH 320         // combined-candidate capacity per half-series
#define SCAP 288         // per-task filtered scratch capacity

#define DATA_WORDS (SPB * RS)                 // 8224
#define CAND_OFF   DATA_WORDS                 // 8224
#define SCR_OFF    (CAND_OFF + 8 * CAPH)      // 10784
#define HIST_OFF   (SCR_OFF + 8 * SCAP)       // 13088
#define REC_OFF    (HIST_OFF + 8 * 256)       // 15136
#define QOUT_OFF   (REC_OFF + 8 * 16)         // 15264
#define SMEM_WORDS (QOUT_OFF + SPB * 8)       // 15296
#define SMEM_BYTES (SMEM_WORDS * 4)           // 61184

__device__ float g_stat2[BB * CC * 16 * 12];   // (b, c, s, j)
__device__ float g_weff[5 * 16 * 16 * 12];     // (cls, c, s, j)

__device__ __forceinline__ unsigned f2key(float x) {
    unsigned b = __float_as_uint(x);
    return b ^ ((unsigned)(((int)b) >> 31) | 0x80000000u);
}
__device__ __forceinline__ float key2f(unsigned k) {
    unsigned u = (k & 0x80000000u) ? (k & 0x7fffffffu) : ~k;
    return __uint_as_float(u);
}

// ---------------------------------------------------------------------------
// 256-bin histogram rank search (warp-uniform r). Returns bin; updates r to
// rank-within-bin; outputs bin count.
// ---------------------------------------------------------------------------
__device__ __forceinline__ int warp_find_bin256(const unsigned* hist, int lane,
                                                int& r, int& bincount) {
    const unsigned full = 0xffffffffu;
    unsigned c[8]; unsigned run = 0;
#pragma unroll
    for (int t = 0; t < 8; t++) { c[t] = hist[lane * 8 + t]; run += c[t]; }
    unsigned inc = run;
#pragma unroll
    for (int d = 1; d < 32; d <<= 1) {
        unsigned v = __shfl_up_sync(full, inc, d);
        if (lane >= d) inc += v;
    }
    unsigned acc = inc - run;
    int bin = -1, newr = 0; unsigned bc = 0;
#pragma unroll
    for (int t = 0; t < 8; t++) {
        if (bin < 0 && (int)acc <= r && r < (int)(acc + c[t])) {
            bin = lane * 8 + t; newr = r - (int)acc; bc = c[t];
        }
        acc += c[t];
    }
    unsigned m = __ballot_sync(full, bin >= 0);
    int srcl = __ffs(m) - 1;
    bin  = __shfl_sync(full, bin, srcl);
    newr = __shfl_sync(full, newr, srcl);
    bc   = __shfl_sync(full, bc, srcl);
    r = newr; bincount = (int)bc;
    return bin;
}

// ---------------------------------------------------------------------------
// Select ranks lr and lr+1 from cnt KEYS in buf (destroyed). k1 valid when
// lr+1 < cnt on entry. Adaptive-shift byte radix + minAbove tracking.
// ---------------------------------------------------------------------------
__device__ uint2 select_keys(unsigned* buf, unsigned* hist, int cnt, int lr,
                             int lane, unsigned kmn, unsigned kmx) {
    const unsigned full = 0xffffffffu;
    unsigned minAbove = 0xffffffffu;
#pragma unroll 1
    while (cnt > 32) {
        unsigned diff = kmn ^ kmx;
        if (diff == 0u) {
            unsigned k1 = (lr + 1 < cnt) ? kmn : minAbove;
            return make_uint2(kmn, k1);
        }
        int hib = 31 - __clz(diff);
        int sh = hib > 7 ? hib - 7 : 0;
#pragma unroll
        for (int t = 0; t < 8; t++) hist[lane + t * 32] = 0u;
        __syncwarp();
        for (int idx = lane; idx < cnt; idx += 32)
            atomicAdd(&hist[(buf[idx] >> sh) & 0xFFu], 1u);
        __syncwarp();
        int bcnt;
        int b = warp_find_bin256(hist, lane, lr, bcnt);
        __syncwarp();
        unsigned nmn = 0xffffffffu, nmx = 0u, mna = 0xffffffffu;
        int nc = 0;
        for (int base = 0; base < cnt; base += 32) {
            int idx = base + lane;
            unsigned kk = (idx < cnt) ? buf[idx] : 0u;
            unsigned bb = (kk >> sh) & 0xFFu;
            bool valid = idx < cnt;
            bool p = valid && (bb == (unsigned)b);
            if (valid && (int)bb > b) mna = min(mna, kk);
            unsigned m = __ballot_sync(full, p);
            __syncwarp();
            if (p) {
                buf[nc + __popc(m & ((1u << lane) - 1u))] = kk;
                nmn = min(nmn, kk); nmx = max(nmx, kk);
            }
            nc += __popc(m);
        }
#pragma unroll
        for (int d = 16; d; d >>= 1) {
            nmn = min(nmn, __shfl_xor_sync(full, nmn, d));
            nmx = max(nmx, __shfl_xor_sync(full, nmx, d));
            mna = min(mna, __shfl_xor_sync(full, mna, d));
        }
        minAbove = min(minAbove, mna);
        kmn = nmn; kmx = nmx; cnt = bcnt;
        __syncwarp();
    }
    unsigned v = (lane < cnt) ? buf[lane] : 0xffffffffu;
#pragma unroll
    for (int k2 = 2; k2 <= 32; k2 <<= 1)
#pragma unroll
        for (int j = k2 >> 1; j; j >>= 1) {
            unsigned o = __shfl_xor_sync(full, v, j);
            bool keepMin = ((lane & j) == 0) == ((lane & k2) == 0);
            v = keepMin ? min(v, o) : max(v, o);
        }
    unsigned k0  = __shfl_sync(full, v, lr);
    unsigned k1n = __shfl_sync(full, v, (lr + 1) & 31);
    unsigned k1  = (lr + 1 < cnt) ? k1n : minAbove;
    return make_uint2(k0, k1);
}

// ---------------------------------------------------------------------------
// Correctness fallback: exact rank-r key via bisection over the intact row.
// ---------------------------------------------------------------------------
__device__ unsigned generic_select_row(const unsigned* row, int lane, int r) {
    const unsigned full = 0xffffffffu;
    unsigned Klo = 0u, Khi = 0xffffffffu;
#pragma unroll 1
    while (Klo < Khi) {
        unsigned mid = Klo + ((Khi - Klo) >> 1);
        int cle = 0;
        for (int i = 0; i < 64; i++)
            cle += (f2key(__uint_as_float(row[i * 32 + lane])) <= mid);
#pragma unroll
        for (int d = 16; d; d >>= 1) cle += __shfl_xor_sync(full, cle, d);
        if (r < cle) Khi = mid; else Klo = mid + 1u;
    }
    return Klo;
}

// ---------------------------------------------------------------------------
// Kernel A: one block per (b,c,part); 4 series, 2 warps per series.
// ---------------------------------------------------------------------------
__global__ __launch_bounds__(NT)
void stats_kernel(const float* __restrict__ features,
                  const float* __restrict__ W2, const float* __restrict__ Wl) {
    extern __shared__ unsigned sm[];
    const unsigned full = 0xffffffffu;

    const int blk  = blockIdx.x;
    const int bc   = blk / NPARTS;
    const int part = blk - bc * NPARTS;       // 0..5 -> joints part*4 .. +3
    const int tid  = threadIdx.x;

    const float* src = features + (size_t)bc * (FF * JT) + part * 4;
    float* smf = reinterpret_cast<float*>(sm);

    // ---- phase 1: load 4 joints, transpose to rows (conflict-free) ----
    {
        int jj = tid & 3;
        int f  = tid >> 2;                    // 0..63
#pragma unroll 8
        for (int k = 0; k < 32; k++, f += 64)
            smf[jj * RS + f] = __ldg(src + f * JT + jj);
    }
    __syncthreads();

    const int w    = tid >> 5;
    const int lane = tid & 31;
    const int s    = w >> 1;                  // series 0..3
    const int h    = w & 1;                   // half 0..1

    // window pivot constants (data ~ N(0,1); fallback covers anything else)
    const float P0 = -0.80f, P1 = -0.55f, P2 = -0.125f,
                P3 =  0.125f, P4 =  0.55f, P5 =  0.80f;

    // ---- phase 2: fused half-scan: moments + counts + combined gather ----
    const unsigned* rowh = sm + s * RS + h * 1024;
    unsigned* cand = sm + CAND_OFF + w * CAPH;
    float s1 = 0.f, s2 = 0.f, s3 = 0.f, s4 = 0.f;
    float mn = INFINITY, mx = -INFINITY;
    int c0 = 0, c1 = 0, c2 = 0;
    int p = 0;                                 // combined window fill
#pragma unroll 4
    for (int i = 0; i < 32; i++) {
        float x = __uint_as_float(rowh[i * 32 + lane]);
        s1 += x;
        float x2 = x * x;
        s2 += x2; s3 += x2 * x; s4 += x2 * x2;
        mn = fminf(mn, x); mx = fmaxf(mx, x);
        bool b0 = x < P0, b1 = x < P1, b2 = x < P2,
             b3 = x < P3, b4 = x < P4, b5 = x < P5;
        c0 += b0; c1 += b2; c2 += b4;
        bool in = (b1 && !b0) || (b3 && !b2) || (b5 && !b4);
        unsigned m = __ballot_sync(full, in);
        if (in) {
            int pos = p + __popc(m & ((1u << lane) - 1u));
            if (pos < CAPH) cand[pos] = __float_as_uint(x);
        }
        p += __popc(m);
    }
#pragma unroll
    for (int d = 16; d; d >>= 1) {
        s1 += __shfl_xor_sync(full, s1, d);
        s2 += __shfl_xor_sync(full, s2, d);
        s3 += __shfl_xor_sync(full, s3, d);
        s4 += __shfl_xor_sync(full, s4, d);
        mn = fminf(mn, __shfl_xor_sync(full, mn, d));
        mx = fmaxf(mx, __shfl_xor_sync(full, mx, d));
        c0 += __shfl_xor_sync(full, c0, d);
        c1 += __shfl_xor_sync(full, c1, d);
        c2 += __shfl_xor_sync(full, c2, d);
    }
    unsigned* rec = sm + REC_OFF + w * 16;
    if (lane == 0) {
        rec[0] = __float_as_uint(s1); rec[1] = __float_as_uint(s2);
        rec[2] = __float_as_uint(s3); rec[3] = __float_as_uint(s4);
        rec[4] = __float_as_uint(mn); rec[5] = __float_as_uint(mx);
        rec[6] = (unsigned)c0; rec[7] = (unsigned)c1; rec[8] = (unsigned)c2;
        rec[9] = (unsigned)p;
    }
    __syncthreads();

    // ---- phase 3: 12 selection tasks over 8 warps ----
    const float PL[3] = {-0.80f, -0.125f, 0.55f};
    const float PH[3] = {-0.55f,  0.125f, 0.80f};
    const int   R0[3] = {511, 1023, 1535};

    unsigned* scr  = sm + SCR_OFF + w * SCAP;
    unsigned* hist = sm + HIST_OFF + w * 256;
    float* qout = reinterpret_cast<float*>(sm + QOUT_OFF);

#pragma unroll 1
    for (int pass = 0; pass < 2; pass++) {
        int t = (pass == 0) ? w : (w < 4 ? 8 + w : -1);
        if (t < 0) break;
        int ts = t / 3, v = t - ts * 3;
        const unsigned* r0 = sm + REC_OFF + (2 * ts) * 16;
        const unsigned* r1 = r0 + 16;
        int clow = (int)r0[6 + v] + (int)r1[6 + v];
        int pa = (int)r0[9], pb = (int)r1[9];
        int lr = R0[v] - clow;
        int need1 = (v != 1);
        float Plo = PL[v], Phi = PH[v];

        // filter combined candidates of both halves into task scratch (keys)
        int cnt = 0;
        unsigned kmn = 0xffffffffu, kmx = 0u;
        bool overflow = (pa > CAPH) || (pb > CAPH);
        if (!overflow) {
#pragma unroll 1
            for (int seg = 0; seg < 2; seg++) {
                const unsigned* cb = sm + CAND_OFF + (2 * ts + seg) * CAPH;
                int pc = seg ? pb : pa;
                for (int base = 0; base < pc; base += 32) {
                    int idx = base + lane;
                    float x = (idx < pc) ? __uint_as_float(cb[idx]) : 0.f;
                    bool in = (idx < pc) && (x >= Plo) && (x < Phi);
                    unsigned m = __ballot_sync(full, in);
                    __syncwarp();
                    if (in) {
                        int pos = cnt + __popc(m & ((1u << lane) - 1u));
                        if (pos < SCAP) {
                            unsigned k = f2key(x);
                            scr[pos] = k;
                            kmn = min(kmn, k); kmx = max(kmx, k);
                        }
                    }
                    cnt += __popc(m);
                }
            }
#pragma unroll
            for (int d = 16; d; d >>= 1) {
                kmn = min(kmn, __shfl_xor_sync(full, kmn, d));
                kmx = max(kmx, __shfl_xor_sync(full, kmx, d));
            }
            __syncwarp();
        }

        bool ok = !overflow && (cnt <= SCAP) && (lr >= 0) &&
                  ((lr + need1) < cnt);
        float v0, v1 = 0.f;
        if (ok) {
            uint2 kk = select_keys(scr, hist, cnt, lr, lane, kmn, kmx);
            v0 = key2f(kk.x);
            if (need1) v1 = key2f(kk.y);
        } else {
            const unsigned* row = sm + ts * RS;
            v0 = key2f(generic_select_row(row, lane, R0[v]));
            if (need1) v1 = key2f(generic_select_row(row, lane, R0[v] + 1));
        }
        if (lane == 0) {
            float* qo = qout + ts * 8;
            if (v == 0) { qo[0] = v0; qo[1] = v1; }
            else if (v == 1) { qo[2] = v0; }
            else { qo[3] = v0; qo[4] = v1; }
        }
    }
    __syncthreads();

    // ---- phase 4: finalize (warp 0, lanes 0..3 -> one series each) ----
    if (w == 0 && lane < SPB) {
        int ts = lane;
        const unsigned* r0 = sm + REC_OFF + (2 * ts) * 16;
        const unsigned* r1 = r0 + 16;
        float ts1 = __uint_as_float(r0[0]) + __uint_as_float(r1[0]);
        float ts2 = __uint_as_float(r0[1]) + __uint_as_float(r1[1]);
        float ts3 = __uint_as_float(r0[2]) + __uint_as_float(r1[2]);
        float ts4 = __uint_as_float(r0[3]) + __uint_as_float(r1[3]);
        float tmn = fminf(__uint_as_float(r0[4]), __uint_as_float(r1[4]));
        float tmx = fmaxf(__uint_as_float(r0[5]), __uint_as_float(r1[5]));
        const float* qo = qout + ts * 8;

        const float n = 2048.f;
        float mean = ts1 / n;
        float m2 = ts2 / n, m3 = ts3 / n, m4 = ts4 / n;
        float varp = m2 - mean * mean;
        float var1 = varp * (n / (n - 1.f));
        float sd = sqrtf(var1);
        float mu2 = mean * mean;
        float m4c = m4 - 4.f * mean * m3 + 6.f * mu2 * m2 - 3.f * mu2 * mu2;
        float kurt = m4c / (var1 * var1) - 3.f;
        float q25 = 0.25f * qo[0] + 0.75f * qo[1];   // pos 511.75
        float med = qo[2];                            // pos 1023
        float q75 = 0.75f * qo[3] + 0.25f * qo[4];   // pos 1535.25

        int jg = part * SPB + ts;                     // 0..23
        int base = (jg < 12) ? 0 : 8;
        int col  = (jg < 12) ? jg : (jg - 12);
        float* o = g_stat2 + ((size_t)bc * 16 + base) * 12 + col;
        o[0 * 12] = tmx;
        o[1 * 12] = q25;
        o[2 * 12] = med;
        o[3 * 12] = q75;
        o[4 * 12] = mean;
        o[5 * 12] = sd;
        o[6 * 12] = tmx - tmn;
        o[7 * 12] = kurt;
    }

    // ---- weff tail folded in: blocks 0..119, threads 0..127 ----
    if (blk < 120 && tid < 128) {
        int idx = blk * 128 + tid;                    // 0 .. 15359
        int j   = idx % 12;
        int sx  = (idx / 12) & 15;
        int cx  = (idx / 192) & 15;
        int cls = idx / 3072;
        float a = 0.f;
#pragma unroll 8
        for (int e = 0; e < 64; e++)
            a += __ldg(&Wl[cls * 1024 + e * 16 + sx]) *
                 __ldg(&W2[(e * 16 + cx) * 12 + j]);
        g_weff[idx] = a;
    }
}

// ---------------------------------------------------------------------------
// Kernel B: logits[b,cls] = dot(stat2[b], weff[cls]) + sum b2*Wl + bl
// ---------------------------------------------------------------------------
__global__ __launch_bounds__(128)
void logits_kernel(const float* __restrict__ Wl, const float* __restrict__ b2,
                   const float* __restrict__ bl, float* __restrict__ out) {
    __shared__ float part[4];
    const unsigned full = 0xffffffffu;
    int blk = blockIdx.x;
    int b = blk / 5, cls = blk - b * 5;
    int tid = threadIdx.x;
    const float* st = g_stat2 + (size_t)b * 3072;
    const float* wf = g_weff + (size_t)cls * 3072;
    float a = 0.f;
    for (int i = tid; i < 3072; i += 128) a += st[i] * wf[i];
    for (int k = tid; k < 1024; k += 128)
        a += __ldg(&b2[k >> 4]) * __ldg(&Wl[cls * 1024 + k]);
#pragma unroll
    for (int d = 16; d; d >>= 1) a += __shfl_xor_sync(full, a, d);
    if ((tid & 31) == 0) part[tid >> 5] = a;
    __syncthreads();
    if (tid == 0)
        out[b * 5 + cls] = part[0] + part[1] + part[2] + part[3] + bl[cls];
}

// ---------------------------------------------------------------------------
extern "C" void kernel_launch(void* const* d_in, const int* in_sizes, int n_in,
                              void* d_out, int out_size) {
    const float* features = (const float*)d_in[0];
    // d_in[1]=W1, d_in[2]=b1 : dead in the reference (result discarded)
    const float* W2 = (const float*)d_in[3];
    const float* b2 = (const float*)d_in[4];
    const float* Wl = (const float*)d_in[5];
    const float* bl = (const float*)d_in[6];
    float* out = (float*)d_out;

    cudaFuncSetAttribute(stats_kernel,
                         cudaFuncAttributeMaxDynamicSharedMemorySize,
                         SMEM_BYTES);

    stats_kernel<<<BB * CC * NPARTS, NT, SMEM_BYTES>>>(features, W2, Wl);
    logits_kernel<<<BB * 5, 128>>>(Wl, b2, bl, out);
}